// round 6
// baseline (speedup 1.0000x reference)
#include <cuda_runtime.h>
#include <cuda_bf16.h>
#include <math.h>

// Global scratch (no allocations allowed). Zero-initialized at module load;
// the elected last block resets both after writing the output, so every
// graph replay starts from the same state.
__device__ double g_acc;
__device__ unsigned int g_count = 0;

#define TPB 256
#define NSTAGE 4
#define CHUNK_ELEMS 256                          // elements per pipeline stage
#define PRED_CHUNK_BYTES (CHUNK_ELEMS * 32)      // 8192 B (32 B per element row)
#define MASK_CHUNK_BYTES (CHUNK_ELEMS)           // 256 B
#define NIT 16                                   // chunks per CTA (contiguous 128KB span)
#define ELEMS_PER_CTA (CHUNK_ELEMS * NIT)        // 4096

__device__ __forceinline__ unsigned smem_u32(const void* p) {
    unsigned a;
    asm("{ .reg .u64 t; cvta.to.shared.u64 t, %1; cvt.u32.u64 %0, t; }"
        : "=r"(a) : "l"(p));
    return a;
}

__device__ __forceinline__ void mbar_wait(unsigned bar, unsigned parity) {
    asm volatile(
        "{\n\t"
        ".reg .pred P1;\n\t"
        "WAIT_LOOP_%=:\n\t"
        "mbarrier.try_wait.parity.acquire.cta.shared::cta.b64 P1, [%0], %1, 0x989680;\n\t"
        "@P1 bra.uni WAIT_DONE_%=;\n\t"
        "bra.uni WAIT_LOOP_%=;\n\t"
        "WAIT_DONE_%=:\n\t"
        "}"
        :: "r"(bar), "r"(parity) : "memory");
}

// Block sum -> global double accumulator; last block writes output & resets.
__device__ __forceinline__ void epilogue(float s, float* out) {
    #pragma unroll
    for (int o = 16; o > 0; o >>= 1)
        s += __shfl_xor_sync(0xFFFFFFFFu, s, o);

    __shared__ float wsum[TPB / 32];
    const int lane = threadIdx.x & 31;
    const int warp = threadIdx.x >> 5;
    if (lane == 0) wsum[warp] = s;
    __syncthreads();

    if (warp == 0 && lane == 0) {
        float bs = 0.0f;
        #pragma unroll
        for (int w = 0; w < TPB / 32; w++) bs += wsum[w];

        atomicAdd(&g_acc, (double)bs);
        __threadfence();
        unsigned c = atomicAdd(&g_count, 1u);
        if (c == gridDim.x - 1) {
            double tot = atomicAdd(&g_acc, 0.0);   // L2-coherent read
            out[0] = (float)(-tot * (1.0 / 256.0));
            g_acc = 0.0;                           // reset for next replay
            g_count = 0;
        }
    }
}

// ---------------------------------------------------------------------------
// Fast path: cp.async.bulk (UBLKCP) staging pipeline. Each CTA streams a
// contiguous 128KB pred span + 4KB mask span through a 4-stage SMEM ring.
// Bulk copies ride the path-independent LTS-cap path (~6300 B/cyc) instead of
// the per-lane 4B-sector LDG path that plateaued at ~5.2 TB/s.
// ---------------------------------------------------------------------------
__global__ void __launch_bounds__(TPB) nll_bulk_kernel(
    const unsigned char* __restrict__ pred_b,   // (n,8) fp32 as bytes
    const unsigned char* __restrict__ mask,     // (n,) bool
    float* __restrict__ out)
{
    __shared__ alignas(128) unsigned char sp[NSTAGE * PRED_CHUNK_BYTES];
    __shared__ alignas(128) unsigned char sm[NSTAGE * MASK_CHUNK_BYTES];
    __shared__ alignas(8)  unsigned long long mbar[NSTAGE];

    const int t = threadIdx.x;
    const size_t base_chunk = (size_t)blockIdx.x * NIT;

    if (t == 0) {
        #pragma unroll
        for (int i = 0; i < NSTAGE; i++) {
            unsigned b = smem_u32(&mbar[i]);
            asm volatile("mbarrier.init.shared.b64 [%0], %1;"
                         :: "r"(b), "r"(1) : "memory");
        }
        asm volatile("fence.proxy.async.shared::cta;" ::: "memory");
    }
    __syncthreads();

    // Producer helper (tid 0 only): arm barrier + issue both bulk copies.
    auto issue = [&](int chunk_local, int stage) {
        size_t chunk = base_chunk + chunk_local;
        unsigned fb = smem_u32(&mbar[stage]);
        asm volatile("mbarrier.arrive.expect_tx.shared.b64 _, [%0], %1;"
                     :: "r"(fb), "r"(PRED_CHUNK_BYTES + MASK_CHUNK_BYTES)
                     : "memory");
        asm volatile(
            "cp.async.bulk.shared::cluster.global.mbarrier::complete_tx::bytes"
            " [%0], [%1], %2, [%3];"
            :: "r"(smem_u32(sp + stage * PRED_CHUNK_BYTES)),
               "l"(pred_b + chunk * PRED_CHUNK_BYTES),
               "r"(PRED_CHUNK_BYTES), "r"(fb) : "memory");
        asm volatile(
            "cp.async.bulk.shared::cluster.global.mbarrier::complete_tx::bytes"
            " [%0], [%1], %2, [%3];"
            :: "r"(smem_u32(sm + stage * MASK_CHUNK_BYTES)),
               "l"(mask + chunk * MASK_CHUNK_BYTES),
               "r"(MASK_CHUNK_BYTES), "r"(fb) : "memory");
    };

    if (t == 0) {
        #pragma unroll
        for (int j = 0; j < NSTAGE; j++) issue(j, j);
    }

    float s = 0.0f;

    for (int it = 0; it < NIT; it++) {
        const int stage = it & (NSTAGE - 1);
        const unsigned parity = (it >> 2) & 1;

        mbar_wait(smem_u32(&mbar[stage]), parity);

        // One element per thread: ch0 float at byte 32*t, mask byte t.
        float p = *(const float*)(sp + stage * PRED_CHUNK_BYTES + t * 32);
        unsigned char m = sm[stage * MASK_CHUNK_BYTES + t];
        // log(p) if masked else log(1-p); 1-p exact for p>=0.5 (Sterbenz),
        // <=0.5ulp otherwise -> noise-level error in a 4M-term sum.
        s += logf(m ? p : 1.0f - p);

        __syncthreads();            // everyone done reading this stage
        if (t == 0 && it + NSTAGE < NIT) issue(it + NSTAGE, stage);
    }

    epilogue(s, out);
}

// Generic fallback for shapes not divisible by ELEMS_PER_CTA.
__global__ void __launch_bounds__(TPB) nll_fallback_kernel(
    const float* __restrict__ pred,
    const unsigned char* __restrict__ mask,
    float* __restrict__ out, int n)
{
    const int tid = blockIdx.x * TPB + threadIdx.x;
    const int stride = gridDim.x * TPB;
    float s = 0.0f;
    #pragma unroll 4
    for (int i = tid; i < n; i += stride) {
        float p = __ldg(&pred[(size_t)i * 8]);
        s += mask[i] ? logf(p) : log1pf(-p);
    }
    epilogue(s, out);
}

extern "C" void kernel_launch(void* const* d_in, const int* in_sizes, int n_in,
                              void* d_out, int out_size)
{
    const float* pred = (const float*)d_in[0];
    const unsigned char* mask = (const unsigned char*)d_in[1];
    float* out = (float*)d_out;

    int n = in_sizes[1];                       // 4,194,304 expected

    if (n > 0 && (n % ELEMS_PER_CTA) == 0) {
        int blocks = n / ELEMS_PER_CTA;        // 1024 for n=4M
        nll_bulk_kernel<<<blocks, TPB>>>(
            (const unsigned char*)pred, mask, out);
    } else {
        int blocks = (n + TPB * 8 - 1) / (TPB * 8);
        if (blocks < 1) blocks = 1;
        if (blocks > 2048) blocks = 2048;
        nll_fallback_kernel<<<blocks, TPB>>>(pred, mask, out, n);
    }
}

// round 7
// speedup vs baseline: 1.0789x; 1.0789x over previous
#include <cuda_runtime.h>
#include <cuda_bf16.h>
#include <math.h>

// Global scratch (no allocations). Zero at module load; the elected last
// block resets both after writing output -> deterministic across replays.
__device__ double g_acc;
__device__ unsigned int g_count = 0;

#define TPB 256
#define ELEMS_PER_CTA 2048
#define PRED_BYTES (ELEMS_PER_CTA * 32)   // 65536
#define MASK_BYTES (ELEMS_PER_CTA)        // 2048
// dyn smem: [mbar: 128B pad][pred: 64KB][mask: 2KB]
#define SM_PRED_OFF 128
#define SM_MASK_OFF (SM_PRED_OFF + PRED_BYTES)
#define SM_TOTAL (SM_MASK_OFF + MASK_BYTES)

__device__ __forceinline__ unsigned smem_u32(const void* p) {
    unsigned a;
    asm("{ .reg .u64 t; cvta.to.shared.u64 t, %1; cvt.u32.u64 %0, t; }"
        : "=r"(a) : "l"(p));
    return a;
}

// Block sum -> global double accumulator; last block writes output & resets.
__device__ __forceinline__ void epilogue(float s, float* out) {
    #pragma unroll
    for (int o = 16; o > 0; o >>= 1)
        s += __shfl_xor_sync(0xFFFFFFFFu, s, o);

    __shared__ float wsum[TPB / 32];
    const int lane = threadIdx.x & 31;
    const int warp = threadIdx.x >> 5;
    if (lane == 0) wsum[warp] = s;
    __syncthreads();

    if (warp == 0 && lane == 0) {
        float bs = 0.0f;
        #pragma unroll
        for (int w = 0; w < TPB / 32; w++) bs += wsum[w];

        atomicAdd(&g_acc, (double)bs);
        __threadfence();
        unsigned c = atomicAdd(&g_count, 1u);
        if (c == gridDim.x - 1) {
            double tot = atomicAdd(&g_acc, 0.0);   // coherent read-back
            out[0] = (float)(-tot * (1.0 / 256.0));
            g_acc = 0.0;
            g_count = 0;
        }
    }
}

// ---------------------------------------------------------------------------
// One 64KB cp.async.bulk per CTA, single mbarrier wait, flat compute.
// 3 CTAs/SM resident -> ~200KB of bulk reads continuously in flight per SM;
// copy-engine occupancy is structural, not consumer-paced.
// ---------------------------------------------------------------------------
__global__ void __launch_bounds__(TPB) nll_bigbulk_kernel(
    const unsigned char* __restrict__ pred_b,   // (n,8) fp32 as bytes
    const unsigned char* __restrict__ mask,     // (n,) bool
    float* __restrict__ out)
{
    extern __shared__ __align__(128) unsigned char dyn[];
    unsigned long long* mbar = (unsigned long long*)dyn;
    unsigned char* sp = dyn + SM_PRED_OFF;
    unsigned char* sm = dyn + SM_MASK_OFF;

    const int t = threadIdx.x;

    if (t == 0) {
        unsigned b = smem_u32(mbar);
        asm volatile("mbarrier.init.shared.b64 [%0], %1;"
                     :: "r"(b), "r"(1) : "memory");
        asm volatile("fence.proxy.async.shared::cta;" ::: "memory");
        asm volatile("mbarrier.arrive.expect_tx.shared.b64 _, [%0], %1;"
                     :: "r"(b), "r"(PRED_BYTES + MASK_BYTES) : "memory");
        asm volatile(
            "cp.async.bulk.shared::cluster.global.mbarrier::complete_tx::bytes"
            " [%0], [%1], %2, [%3];"
            :: "r"(smem_u32(sp)),
               "l"(pred_b + (size_t)blockIdx.x * PRED_BYTES),
               "r"(PRED_BYTES), "r"(b) : "memory");
        asm volatile(
            "cp.async.bulk.shared::cluster.global.mbarrier::complete_tx::bytes"
            " [%0], [%1], %2, [%3];"
            :: "r"(smem_u32(sm)),
               "l"(mask + (size_t)blockIdx.x * MASK_BYTES),
               "r"(MASK_BYTES), "r"(b) : "memory");
    }
    __syncthreads();   // all threads see initialized barrier before waiting

    {
        unsigned b = smem_u32(mbar);
        asm volatile(
            "{\n\t"
            ".reg .pred P1;\n\t"
            "WAIT_LOOP_%=:\n\t"
            "mbarrier.try_wait.parity.acquire.cta.shared::cta.b64 P1, [%0], 0, 0x989680;\n\t"
            "@P1 bra.uni WAIT_DONE_%=;\n\t"
            "bra.uni WAIT_LOOP_%=;\n\t"
            "WAIT_DONE_%=:\n\t"
            "}"
            :: "r"(b) : "memory");
    }

    float s = 0.0f;
    #pragma unroll
    for (int k = 0; k < ELEMS_PER_CTA / TPB; k++) {
        int e = t + k * TPB;
        float p = *(const float*)(sp + (size_t)e * 32);
        unsigned char m = sm[e];
        // log(p) if masked else log(1-p). 1-p exact for p>=0.5 (Sterbenz),
        // <=0.5ulp otherwise -> noise-level in a 4M-term sum at 1e-3 tol.
        s += logf(m ? p : 1.0f - p);
    }

    epilogue(s, out);
}

// Generic fallback for shapes not divisible by ELEMS_PER_CTA.
__global__ void __launch_bounds__(TPB) nll_fallback_kernel(
    const float* __restrict__ pred,
    const unsigned char* __restrict__ mask,
    float* __restrict__ out, int n)
{
    const int tid = blockIdx.x * TPB + threadIdx.x;
    const int stride = gridDim.x * TPB;
    float s = 0.0f;
    #pragma unroll 4
    for (int i = tid; i < n; i += stride) {
        float p = __ldg(&pred[(size_t)i * 8]);
        s += mask[i] ? logf(p) : log1pf(-p);
    }
    epilogue(s, out);
}

extern "C" void kernel_launch(void* const* d_in, const int* in_sizes, int n_in,
                              void* d_out, int out_size)
{
    const float* pred = (const float*)d_in[0];
    const unsigned char* mask = (const unsigned char*)d_in[1];
    float* out = (float*)d_out;

    int n = in_sizes[1];                       // 4,194,304 expected

    if (n > 0 && (n % ELEMS_PER_CTA) == 0) {
        // Not an allocation: raises the dynamic-smem cap for this kernel.
        cudaFuncSetAttribute(nll_bigbulk_kernel,
                             cudaFuncAttributeMaxDynamicSharedMemorySize,
                             SM_TOTAL);
        int blocks = n / ELEMS_PER_CTA;        // 2048 for n=4M
        nll_bigbulk_kernel<<<blocks, TPB, SM_TOTAL>>>(
            (const unsigned char*)pred, mask, out);
    } else {
        int blocks = (n + TPB * 8 - 1) / (TPB * 8);
        if (blocks < 1) blocks = 1;
        if (blocks > 2048) blocks = 2048;
        nll_fallback_kernel<<<blocks, TPB>>>(pred, mask, out, n);
    }
}

// round 9
// speedup vs baseline: 1.1604x; 1.0755x over previous
#include <cuda_runtime.h>
#include <cuda_bf16.h>
#include <math.h>

// Scratch (no allocations allowed): per-block partials + completion counter.
// Every g_part slot used in a launch is rewritten that launch; g_count
// self-resets to 0 in the last block -> deterministic across graph replays.
#define MAX_BLOCKS 4096
__device__ float g_part[MAX_BLOCKS];
__device__ unsigned int g_count = 0;

#define TPB 256
#define ILP 8

__global__ void __launch_bounds__(TPB) nll_fused_kernel(
    const float* __restrict__ pred,          // (n, 8) fp32, channel 0 used
    const unsigned char* __restrict__ mask,  // (n,) bool (1 byte)
    float* __restrict__ out,
    int n)
{
    const int tid = blockIdx.x * TPB + threadIdx.x;
    const int stride = gridDim.x * TPB;

    float s = 0.0f;

    if (n == stride * ILP) {
        // Fast path: exactly ILP strided elements per thread, fully
        // front-batched (16 independent LDGs before any consumer).
        // ld.global.cs.L2::256B = streaming eviction + 256B L2 miss-fetch
        // granule: fewer/longer DRAM bursts on this perfectly-sequential
        // 132MB stream (the dense layout means the wider fetch is never
        // wasted). Lanes hit consecutive 32B sectors (row stride = 8 floats).
        float p[ILP];
        unsigned int mword[ILP];
        #pragma unroll
        for (int k = 0; k < ILP; k++) {
            int e = tid + k * stride;
            asm volatile("ld.global.cs.L2::256B.f32 %0, [%1];"
                         : "=f"(p[k]) : "l"(&pred[(size_t)e * 8]));
        }
        #pragma unroll
        for (int k = 0; k < ILP; k++) {
            int e = tid + k * stride;
            asm volatile("ld.global.cs.L2::256B.u8 %0, [%1];"
                         : "=r"(mword[k]) : "l"(&mask[e]));
        }
        #pragma unroll
        for (int k = 0; k < ILP; k++) {
            // log(p) if masked else log(1-p). 1-p is exact for p>=0.5
            // (Sterbenz) and <=0.5ulp otherwise: per-element error ~2e-7,
            // random sign -> invisible in the 4M-term sum at 1e-3 tol.
            float q = mword[k] ? p[k] : 1.0f - p[k];
            s += logf(q);
        }
    } else {
        // Generic fallback (any n).
        #pragma unroll 4
        for (int i = tid; i < n; i += stride) {
            float p = __ldg(&pred[(size_t)i * 8]);
            s += mask[i] ? logf(p) : log1pf(-p);
        }
    }

    // Warp reduction.
    #pragma unroll
    for (int o = 16; o > 0; o >>= 1)
        s += __shfl_xor_sync(0xFFFFFFFFu, s, o);

    __shared__ float warp_sums[TPB / 32];
    const int lane = threadIdx.x & 31;
    const int warp = threadIdx.x >> 5;
    if (lane == 0) warp_sums[warp] = s;
    __syncthreads();

    if (warp == 0) {
        float bs = (lane < (TPB >> 5)) ? warp_sums[lane] : 0.0f;
        #pragma unroll
        for (int o = 4; o > 0; o >>= 1)
            bs += __shfl_xor_sync(0xFFFFFFFFu, bs, o);
        if (lane == 0) g_part[blockIdx.x] = bs;
    }

    // Elect the last block to finish (threadfence-reduction pattern).
    __shared__ bool is_last;
    __threadfence();
    if (threadIdx.x == 0) {
        unsigned int c = atomicAdd(&g_count, 1u);
        is_last = (c == gridDim.x - 1);
    }
    __syncthreads();

    if (is_last) {
        double d = 0.0;
        for (int i = threadIdx.x; i < (int)gridDim.x; i += TPB)
            d += (double)g_part[i];

        #pragma unroll
        for (int o = 16; o > 0; o >>= 1)
            d += __shfl_xor_sync(0xFFFFFFFFu, d, o);

        __shared__ double dwarp[TPB / 32];
        if (lane == 0) dwarp[warp] = d;
        __syncthreads();
        if (warp == 0) {
            double bd = (lane < (TPB >> 5)) ? dwarp[lane] : 0.0;
            #pragma unroll
            for (int o = 4; o > 0; o >>= 1)
                bd += __shfl_xor_sync(0xFFFFFFFFu, bd, o);
            if (lane == 0) {
                out[0] = (float)(-bd * (1.0 / 256.0));
                g_count = 0;  // self-reset for next graph replay
            }
        }
    }
}

extern "C" void kernel_launch(void* const* d_in, const int* in_sizes, int n_in,
                              void* d_out, int out_size)
{
    const float* pred = (const float*)d_in[0];
    const unsigned char* mask = (const unsigned char*)d_in[1];
    float* out = (float*)d_out;

    int n = in_sizes[1];                             // 4,194,304 expected

    int blocks = (n + TPB * ILP - 1) / (TPB * ILP);  // 2048 for n=4M
    if (blocks > MAX_BLOCKS) blocks = MAX_BLOCKS;    // fallback path handles rest
    if (blocks < 1) blocks = 1;

    nll_fused_kernel<<<blocks, TPB>>>(pred, mask, out, n);
}